// round 10
// baseline (speedup 1.0000x reference)
#include <cuda_runtime.h>

// Problem constants (from reference config)
#define BB 2
#define NN 6
#define DD 48
#define FH 16
#define FW 44
#define CC 80
#define NX 256
#define NY 256

#define NCHUNK (CC/4)                 // 20 float4 chunks per point
#define NGROUP (BB*NN*DD*FW)          // 25344 (b,n,d,w) groups
#define NTHREAD (NGROUP*NCHUNK)       // 506880
#define TPB 256
#define PLANE (NY*NX)                 // 65536
#define NSCR (BB*PLANE*CC)            // scratch floats (41.9MB)
#define NSCR4 (NSCR/4)

// per-group classification: >=0 uniform voxel, -1 all dropped, -2 mixed
__device__ int g_cls[NGROUP];
__device__ int g_svox[NGROUP][FH];    // per-h voxel, written only for mixed groups
// channel-contiguous accumulator: [B, Y*X, C]
__device__ float g_scratch[NSCR];

__device__ __forceinline__ void inv3(const float* m, float* o) {
    float a = m[0], b = m[1], c = m[2];
    float d = m[3], e = m[4], f = m[5];
    float g = m[6], h = m[7], i = m[8];
    float A = e * i - f * h;
    float B = -(d * i - f * g);
    float Cc = d * h - e * g;
    float det = a * A + b * B + c * Cc;
    float id = 1.0f / det;
    o[0] = A * id;
    o[1] = -(b * i - c * h) * id;
    o[2] = (b * f - c * e) * id;
    o[3] = B * id;
    o[4] = (a * i - c * g) * id;
    o[5] = -(a * f - c * d) * id;
    o[6] = Cc * id;
    o[7] = -(a * h - b * g) * id;
    o[8] = (a * e - b * d) * id;
}

__device__ __forceinline__ void red_v4(float* p, float4 v) {
    asm volatile("red.global.add.v4.f32 [%0], {%1, %2, %3, %4};"
                 :: "l"(p), "f"(v.x), "f"(v.y), "f"(v.z), "f"(v.w) : "memory");
}

// Fused: zero the scratch (bandwidth-bound) + per-group geometry (hidden under it)
__global__ void __launch_bounds__(TPB)
prep_kernel(const float* __restrict__ rots,
            const float* __restrict__ trans,
            const float* __restrict__ intrins,
            const float* __restrict__ post_rots,
            const float* __restrict__ post_trans) {
    int t = blockIdx.x * TPB + threadIdx.x;
    if (t < NSCR4)
        reinterpret_cast<float4*>(g_scratch)[t] = make_float4(0.f, 0.f, 0.f, 0.f);

    if (t >= NGROUP) return;
    int grp = t;
    int w = grp % FW;
    int rem = grp / FW;
    int d = rem % DD;
    int cam = rem / DD;

    float invK[9], invP[9], comb[9];
    inv3(intrins + cam * 9, invK);
    inv3(post_rots + cam * 9, invP);
    {
        const float* R = rots + cam * 9;
        #pragma unroll
        for (int i = 0; i < 3; i++)
            #pragma unroll
            for (int k = 0; k < 3; k++)
                comb[i * 3 + k] = R[i * 3 + 0] * invK[0 * 3 + k]
                                + R[i * 3 + 1] * invK[1 * 3 + k]
                                + R[i * 3 + 2] * invK[2 * 3 + k];
    }
    float t0 = trans[cam * 3 + 0], t1 = trans[cam * 3 + 1], t2 = trans[cam * 3 + 2];
    float pt0 = post_trans[cam * 3 + 0], pt1 = post_trans[cam * 3 + 1], pt2 = post_trans[cam * 3 + 2];

    float u = (float)w * (703.0f / 43.0f);       // linspace(0, 703, 44)
    float dep = 2.0f + (float)d * (56.0f / 48.0f);

    int vox[FH];
    #pragma unroll
    for (int h = 0; h < FH; h++) {
        float v = (float)h * 17.0f;              // linspace(0, 255, 16)
        float a0 = u - pt0, a1 = v - pt1, a2 = dep - pt2;
        float q0 = invP[0] * a0 + invP[1] * a1 + invP[2] * a2;
        float q1 = invP[3] * a0 + invP[4] * a1 + invP[5] * a2;
        float q2 = invP[6] * a0 + invP[7] * a1 + invP[8] * a2;
        float r0 = q0 * q2, r1 = q1 * q2, r2 = q2;
        float ex = comb[0] * r0 + comb[1] * r1 + comb[2] * r2 + t0;
        float ey = comb[3] * r0 + comb[4] * r1 + comb[5] * r2 + t1;
        float ez = comb[6] * r0 + comb[7] * r1 + comb[8] * r2 + t2;
        int gx = (int)((ex + 51.2f) / 0.4f);     // trunc-toward-zero == astype(int32)
        int gy = (int)((ey + 51.2f) / 0.4f);
        int gz = (int)((ez + 10.0f) / 20.0f);
        bool kept = (gx >= 0) & (gx < NX) & (gy >= 0) & (gy < NY) & (gz == 0);
        vox[h] = kept ? (gy * NX + gx) : -1;
    }

    int first = vox[0];
    bool uniform = true;
    bool anyvalid = false;
    #pragma unroll
    for (int h = 0; h < FH; h++) {
        uniform &= (vox[h] == first);
        anyvalid |= (vox[h] >= 0);
    }

    int cls;
    if (!anyvalid) cls = -1;
    else if (uniform && first >= 0) cls = first;
    else {
        cls = -2;
        #pragma unroll
        for (int h = 0; h < FH; h++) g_svox[grp][h] = vox[h];
    }
    g_cls[grp] = cls;
}

// Lean pool: 1 broadcast class load -> 16 branch-free loads -> 1 vector RED
__global__ void __launch_bounds__(TPB, 6)
pool_kernel(const float* __restrict__ x) {
    int g = blockIdx.x * TPB + threadIdx.x;

    int chunk = g % NCHUNK;
    int grp = g / NCHUNK;
    int cls = g_cls[grp];
    if (cls == -1) return;                       // whole column dropped

    int gd = grp / FW;                           // cam*DD + d
    int w = grp - gd * FW;
    int b = grp / (NN * DD * FW);

    const float* xp = x + (((size_t)gd * FH * FW + w) * CC) + chunk * 4;
    const int hstride = FW * CC;                 // 3520 floats
    float* sbase = g_scratch + (size_t)b * (PLANE * CC) + chunk * 4;

    if (cls >= 0) {
        // dominant case: branch-free, 16 independent streaming loads
        float4 acc = make_float4(0.f, 0.f, 0.f, 0.f);
        #pragma unroll
        for (int h = 0; h < FH; h++) {
            float4 val = __ldcs(reinterpret_cast<const float4*>(xp + h * hstride));
            acc.x += val.x;
            acc.y += val.y;
            acc.z += val.z;
            acc.w += val.w;
        }
        red_v4(sbase + (size_t)cls * CC, acc);
        return;
    }

    // mixed column (rare): run-length accumulate using per-h table
    float4 acc = make_float4(0.f, 0.f, 0.f, 0.f);
    int cur = -1;
    #pragma unroll 1
    for (int h = 0; h < FH; h++) {
        int vox = g_svox[grp][h];
        if (vox >= 0) {
            if (vox != cur) {
                if (cur >= 0) red_v4(sbase + (size_t)cur * CC, acc);
                acc = make_float4(0.f, 0.f, 0.f, 0.f);
                cur = vox;
            }
            float4 val = __ldcs(reinterpret_cast<const float4*>(xp + h * hstride));
            acc.x += val.x;
            acc.y += val.y;
            acc.z += val.z;
            acc.w += val.w;
        }
    }
    if (cur >= 0) red_v4(sbase + (size_t)cur * CC, acc);
}

// Transpose scratch [B, Y, X, C] -> out [B, C, Y, X]; tile = 32 x-positions.
__global__ void __launch_bounds__(TPB)
transpose_kernel(float* __restrict__ out) {
    __shared__ float tile[CC][36];               // [c][x], row 144B (16B aligned)
    int bx = blockIdx.x;                          // 0..7  (x tile)
    int y  = blockIdx.y;                          // 0..255
    int b  = blockIdx.z;                          // 0..1
    int tid = threadIdx.x;

    const float4* src = reinterpret_cast<const float4*>(g_scratch)
                      + ((size_t)b * PLANE + y * NX + bx * 32) * NCHUNK;

    // load 32 x * 20 c4 float4; warp-fixed c4 -> conflict-free scalar STS
    #pragma unroll
    for (int i = tid; i < 32 * NCHUNK; i += TPB) {
        int xx = i & 31, c4 = i >> 5;
        float4 v = src[(size_t)xx * NCHUNK + c4];
        tile[c4 * 4 + 0][xx] = v.x;
        tile[c4 * 4 + 1][xx] = v.y;
        tile[c4 * 4 + 2][xx] = v.z;
        tile[c4 * 4 + 3][xx] = v.w;
    }
    __syncthreads();

    // write out: 80 c-rows x 8 float4 (128B per 8 lanes, coalesced)
    #pragma unroll
    for (int i = tid; i < CC * 8; i += TPB) {
        int c = i >> 3, xq = i & 7;
        float4 v = *reinterpret_cast<const float4*>(&tile[c][xq * 4]);
        float* optr = out + ((size_t)(b * CC + c)) * PLANE + y * NX + bx * 32 + xq * 4;
        *reinterpret_cast<float4*>(optr) = v;
    }
}

extern "C" void kernel_launch(void* const* d_in, const int* in_sizes, int n_in,
                              void* d_out, int out_size) {
    const float* x          = (const float*)d_in[0];
    const float* rots       = (const float*)d_in[1];
    const float* trans      = (const float*)d_in[2];
    const float* intrins    = (const float*)d_in[3];
    const float* post_rots  = (const float*)d_in[4];
    const float* post_trans = (const float*)d_in[5];
    float* out = (float*)d_out;

    prep_kernel<<<(NSCR4 + TPB - 1) / TPB, TPB>>>(rots, trans, intrins, post_rots,
                                                  post_trans);

    pool_kernel<<<NTHREAD / TPB, TPB>>>(x);

    transpose_kernel<<<dim3(NX / 32, NY, BB), TPB>>>(out);
}

// round 13
// speedup vs baseline: 1.1709x; 1.1709x over previous
#include <cuda_runtime.h>

// Problem constants (from reference config)
#define BB 2
#define NN 6
#define DD 48
#define FH 16
#define FW 44
#define CC 80
#define NX 256
#define NY 256

#define NCHUNK (CC/4)                 // 20 float4 chunks per point
#define NGROUP (BB*NN*DD*FW)          // 25344 (b,n,d,w) groups
#define HSPLIT 2
#define HPER (FH/HSPLIT)              // 8 h per thread
#define NTHREAD2 (NGROUP*NCHUNK*HSPLIT)  // 1013760
#define TPB 256
#define PTPB 128
#define PLANE (NY*NX)                 // 65536

// per-group classification: >=0 uniform voxel, -1 all dropped, -2 mixed
__device__ int g_cls[NGROUP];
__device__ int g_svox[NGROUP][FH];    // per-h voxel, written only for mixed groups

__device__ __forceinline__ void inv3(const float* m, float* o) {
    float a = m[0], b = m[1], c = m[2];
    float d = m[3], e = m[4], f = m[5];
    float g = m[6], h = m[7], i = m[8];
    float A = e * i - f * h;
    float B = -(d * i - f * g);
    float Cc = d * h - e * g;
    float det = a * A + b * B + c * Cc;
    float id = 1.0f / det;
    o[0] = A * id;
    o[1] = -(b * i - c * h) * id;
    o[2] = (b * f - c * e) * id;
    o[3] = B * id;
    o[4] = (a * i - c * g) * id;
    o[5] = -(a * f - c * d) * id;
    o[6] = Cc * id;
    o[7] = -(a * h - b * g) * id;
    o[8] = (a * e - b * d) * id;
}

// Fused: zero the output (bandwidth-bound) + per-group geometry (hidden under it)
__global__ void __launch_bounds__(TPB)
prep_kernel(float4* __restrict__ out4, int n4,
            const float* __restrict__ rots,
            const float* __restrict__ trans,
            const float* __restrict__ intrins,
            const float* __restrict__ post_rots,
            const float* __restrict__ post_trans) {
    int t = blockIdx.x * TPB + threadIdx.x;
    if (t < n4) out4[t] = make_float4(0.f, 0.f, 0.f, 0.f);

    if (t >= NGROUP) return;
    int grp = t;
    int w = grp % FW;
    int rem = grp / FW;
    int d = rem % DD;
    int cam = rem / DD;

    float invK[9], invP[9], comb[9];
    inv3(intrins + cam * 9, invK);
    inv3(post_rots + cam * 9, invP);
    {
        const float* R = rots + cam * 9;
        #pragma unroll
        for (int i = 0; i < 3; i++)
            #pragma unroll
            for (int k = 0; k < 3; k++)
                comb[i * 3 + k] = R[i * 3 + 0] * invK[0 * 3 + k]
                                + R[i * 3 + 1] * invK[1 * 3 + k]
                                + R[i * 3 + 2] * invK[2 * 3 + k];
    }
    float t0 = trans[cam * 3 + 0], t1 = trans[cam * 3 + 1], t2 = trans[cam * 3 + 2];
    float pt0 = post_trans[cam * 3 + 0], pt1 = post_trans[cam * 3 + 1], pt2 = post_trans[cam * 3 + 2];

    float u = (float)w * (703.0f / 43.0f);       // linspace(0, 703, 44)
    float dep = 2.0f + (float)d * (56.0f / 48.0f);

    int vox[FH];
    #pragma unroll
    for (int h = 0; h < FH; h++) {
        float v = (float)h * 17.0f;              // linspace(0, 255, 16)
        float a0 = u - pt0, a1 = v - pt1, a2 = dep - pt2;
        float q0 = invP[0] * a0 + invP[1] * a1 + invP[2] * a2;
        float q1 = invP[3] * a0 + invP[4] * a1 + invP[5] * a2;
        float q2 = invP[6] * a0 + invP[7] * a1 + invP[8] * a2;
        float r0 = q0 * q2, r1 = q1 * q2, r2 = q2;
        float ex = comb[0] * r0 + comb[1] * r1 + comb[2] * r2 + t0;
        float ey = comb[3] * r0 + comb[4] * r1 + comb[5] * r2 + t1;
        float ez = comb[6] * r0 + comb[7] * r1 + comb[8] * r2 + t2;
        int gx = (int)((ex + 51.2f) / 0.4f);     // trunc-toward-zero == astype(int32)
        int gy = (int)((ey + 51.2f) / 0.4f);
        int gz = (int)((ez + 10.0f) / 20.0f);
        bool kept = (gx >= 0) & (gx < NX) & (gy >= 0) & (gy < NY) & (gz == 0);
        vox[h] = kept ? (gy * NX + gx) : -1;
    }

    int first = vox[0];
    bool uniform = true;
    bool anyvalid = false;
    #pragma unroll
    for (int h = 0; h < FH; h++) {
        uniform &= (vox[h] == first);
        anyvalid |= (vox[h] >= 0);
    }

    int cls;
    if (!anyvalid) cls = -1;
    else if (uniform && first >= 0) cls = first;
    else {
        cls = -2;
        #pragma unroll
        for (int h = 0; h < FH; h++) g_svox[grp][h] = vox[h];
    }
    g_cls[grp] = cls;
}

// Lean pool: thread = (h-half, group, chunk). 8 branch-free loads -> 4 REDs.
__global__ void __launch_bounds__(PTPB, 12)
pool_kernel(const float* __restrict__ x, float* __restrict__ out) {
    int g = blockIdx.x * PTPB + threadIdx.x;

    int chunk = g % NCHUNK;
    int rest = g / NCHUNK;
    int grp = rest % NGROUP;                     // lane-consecutive => grp-consecutive
    int hh = rest / NGROUP;                      // 0 or 1
    int cls = g_cls[grp];
    if (cls == -1) return;                       // whole column dropped

    int gd = grp / FW;                           // cam*DD + d
    int w = grp - gd * FW;
    int b = grp / (NN * DD * FW);
    int h0 = hh * HPER;

    const float* xp = x + (((size_t)gd * FH * FW + (size_t)h0 * FW + w) * CC) + chunk * 4;
    const int hstride = FW * CC;                 // 3520 floats
    float* obase = out + (size_t)(b * CC + chunk * 4) * PLANE;

    if (cls >= 0) {
        // dominant case: branch-free, 8 independent streaming loads
        float4 acc = make_float4(0.f, 0.f, 0.f, 0.f);
        #pragma unroll
        for (int h = 0; h < HPER; h++) {
            float4 val = __ldcs(reinterpret_cast<const float4*>(xp + h * hstride));
            acc.x += val.x;
            acc.y += val.y;
            acc.z += val.z;
            acc.w += val.w;
        }
        float* o = obase + cls;
        atomicAdd(o, acc.x);
        atomicAdd(o + PLANE, acc.y);
        atomicAdd(o + 2 * PLANE, acc.z);
        atomicAdd(o + 3 * PLANE, acc.w);
        return;
    }

    // mixed column (rare): run-length accumulate over this thread's h-half
    float4 acc = make_float4(0.f, 0.f, 0.f, 0.f);
    int cur = -1;
    #pragma unroll 1
    for (int h = 0; h < HPER; h++) {
        int vox = g_svox[grp][h0 + h];
        if (vox >= 0) {
            if (vox != cur) {
                if (cur >= 0) {
                    float* o = obase + cur;
                    atomicAdd(o, acc.x);
                    atomicAdd(o + PLANE, acc.y);
                    atomicAdd(o + 2 * PLANE, acc.z);
                    atomicAdd(o + 3 * PLANE, acc.w);
                }
                acc = make_float4(0.f, 0.f, 0.f, 0.f);
                cur = vox;
            }
            float4 val = __ldcs(reinterpret_cast<const float4*>(xp + h * hstride));
            acc.x += val.x;
            acc.y += val.y;
            acc.z += val.z;
            acc.w += val.w;
        }
    }
    if (cur >= 0) {
        float* o = obase + cur;
        atomicAdd(o, acc.x);
        atomicAdd(o + PLANE, acc.y);
        atomicAdd(o + 2 * PLANE, acc.z);
        atomicAdd(o + 3 * PLANE, acc.w);
    }
}

extern "C" void kernel_launch(void* const* d_in, const int* in_sizes, int n_in,
                              void* d_out, int out_size) {
    const float* x          = (const float*)d_in[0];
    const float* rots       = (const float*)d_in[1];
    const float* trans      = (const float*)d_in[2];
    const float* intrins    = (const float*)d_in[3];
    const float* post_rots  = (const float*)d_in[4];
    const float* post_trans = (const float*)d_in[5];
    float* out = (float*)d_out;

    int n4 = out_size / 4;
    prep_kernel<<<(n4 + TPB - 1) / TPB, TPB>>>((float4*)out, n4, rots, trans,
                                               intrins, post_rots, post_trans);

    pool_kernel<<<NTHREAD2 / PTPB, PTPB>>>(x, out);
}

// round 14
// speedup vs baseline: 1.2369x; 1.0563x over previous
#include <cuda_runtime.h>

// Problem constants (from reference config)
#define BB 2
#define NN 6
#define DD 48
#define FH 16
#define FW 44
#define CC 80
#define NX 256
#define NY 256

#define NCHUNK (CC/4)                 // 20 float4 chunks per point
#define NGROUP (BB*NN*DD*FW)          // 25344 (b,n,d,w) groups
#define NTHREAD (NGROUP*NCHUNK)       // 506880
#define TPB 256
#define UNITS (NTHREAD/TPB)           // 1980 unit-blocks
#define OCC 6
#define NCTA (148*OCC)                // 888 persistent CTAs
#define PLANE (NY*NX)                 // 65536

// per-group classification: >=0 uniform voxel, -1 all dropped, -2 mixed
__device__ int g_cls[NGROUP];
__device__ int g_svox[NGROUP][FH];    // per-h voxel, written only for mixed groups

__device__ __forceinline__ void inv3(const float* m, float* o) {
    float a = m[0], b = m[1], c = m[2];
    float d = m[3], e = m[4], f = m[5];
    float g = m[6], h = m[7], i = m[8];
    float A = e * i - f * h;
    float B = -(d * i - f * g);
    float Cc = d * h - e * g;
    float det = a * A + b * B + c * Cc;
    float id = 1.0f / det;
    o[0] = A * id;
    o[1] = -(b * i - c * h) * id;
    o[2] = (b * f - c * e) * id;
    o[3] = B * id;
    o[4] = (a * i - c * g) * id;
    o[5] = -(a * f - c * d) * id;
    o[6] = Cc * id;
    o[7] = -(a * h - b * g) * id;
    o[8] = (a * e - b * d) * id;
}

// Fused: zero the output (bandwidth-bound) + per-group geometry (hidden under it)
__global__ void __launch_bounds__(TPB)
prep_kernel(float4* __restrict__ out4, int n4,
            const float* __restrict__ rots,
            const float* __restrict__ trans,
            const float* __restrict__ intrins,
            const float* __restrict__ post_rots,
            const float* __restrict__ post_trans) {
    int t = blockIdx.x * TPB + threadIdx.x;
    if (t < n4) out4[t] = make_float4(0.f, 0.f, 0.f, 0.f);

    if (t >= NGROUP) return;
    int grp = t;
    int w = grp % FW;
    int rem = grp / FW;
    int d = rem % DD;
    int cam = rem / DD;

    float invK[9], invP[9], comb[9];
    inv3(intrins + cam * 9, invK);
    inv3(post_rots + cam * 9, invP);
    {
        const float* R = rots + cam * 9;
        #pragma unroll
        for (int i = 0; i < 3; i++)
            #pragma unroll
            for (int k = 0; k < 3; k++)
                comb[i * 3 + k] = R[i * 3 + 0] * invK[0 * 3 + k]
                                + R[i * 3 + 1] * invK[1 * 3 + k]
                                + R[i * 3 + 2] * invK[2 * 3 + k];
    }
    float t0 = trans[cam * 3 + 0], t1 = trans[cam * 3 + 1], t2 = trans[cam * 3 + 2];
    float pt0 = post_trans[cam * 3 + 0], pt1 = post_trans[cam * 3 + 1], pt2 = post_trans[cam * 3 + 2];

    float u = (float)w * (703.0f / 43.0f);       // linspace(0, 703, 44)
    float dep = 2.0f + (float)d * (56.0f / 48.0f);

    int vox[FH];
    #pragma unroll
    for (int h = 0; h < FH; h++) {
        float v = (float)h * 17.0f;              // linspace(0, 255, 16)
        float a0 = u - pt0, a1 = v - pt1, a2 = dep - pt2;
        float q0 = invP[0] * a0 + invP[1] * a1 + invP[2] * a2;
        float q1 = invP[3] * a0 + invP[4] * a1 + invP[5] * a2;
        float q2 = invP[6] * a0 + invP[7] * a1 + invP[8] * a2;
        float r0 = q0 * q2, r1 = q1 * q2, r2 = q2;
        float ex = comb[0] * r0 + comb[1] * r1 + comb[2] * r2 + t0;
        float ey = comb[3] * r0 + comb[4] * r1 + comb[5] * r2 + t1;
        float ez = comb[6] * r0 + comb[7] * r1 + comb[8] * r2 + t2;
        int gx = (int)((ex + 51.2f) / 0.4f);     // trunc-toward-zero == astype(int32)
        int gy = (int)((ey + 51.2f) / 0.4f);
        int gz = (int)((ez + 10.0f) / 20.0f);
        bool kept = (gx >= 0) & (gx < NX) & (gy >= 0) & (gy < NY) & (gz == 0);
        vox[h] = kept ? (gy * NX + gx) : -1;
    }

    int first = vox[0];
    bool uniform = true;
    bool anyvalid = false;
    #pragma unroll
    for (int h = 0; h < FH; h++) {
        uniform &= (vox[h] == first);
        anyvalid |= (vox[h] >= 0);
    }

    int cls;
    if (!anyvalid) cls = -1;
    else if (uniform && first >= 0) cls = first;
    else {
        cls = -2;
        #pragma unroll
        for (int h = 0; h < FH; h++) g_svox[grp][h] = vox[h];
    }
    g_cls[grp] = cls;
}

__device__ __forceinline__ void pool_unit(int g, const float* __restrict__ x,
                                          float* __restrict__ out) {
    int chunk = g % NCHUNK;
    int grp = g / NCHUNK;
    int cls = g_cls[grp];
    if (cls == -1) return;                       // whole column dropped

    int gd = grp / FW;                           // cam*DD + d
    int w = grp - gd * FW;
    int b = grp / (NN * DD * FW);

    const float* xp = x + (((size_t)gd * FH * FW + w) * CC) + chunk * 4;
    const int hstride = FW * CC;                 // 3520 floats
    float* obase = out + (size_t)(b * CC + chunk * 4) * PLANE;

    if (cls >= 0) {
        // dominant case: branch-free, 16 independent streaming loads
        float4 acc = make_float4(0.f, 0.f, 0.f, 0.f);
        #pragma unroll
        for (int h = 0; h < FH; h++) {
            float4 val = __ldcs(reinterpret_cast<const float4*>(xp + h * hstride));
            acc.x += val.x;
            acc.y += val.y;
            acc.z += val.z;
            acc.w += val.w;
        }
        float* o = obase + cls;
        atomicAdd(o, acc.x);
        atomicAdd(o + PLANE, acc.y);
        atomicAdd(o + 2 * PLANE, acc.z);
        atomicAdd(o + 3 * PLANE, acc.w);
        return;
    }

    // mixed column (rare): run-length accumulate using per-h table
    float4 acc = make_float4(0.f, 0.f, 0.f, 0.f);
    int cur = -1;
    #pragma unroll 1
    for (int h = 0; h < FH; h++) {
        int vox = g_svox[grp][h];
        if (vox >= 0) {
            if (vox != cur) {
                if (cur >= 0) {
                    float* o = obase + cur;
                    atomicAdd(o, acc.x);
                    atomicAdd(o + PLANE, acc.y);
                    atomicAdd(o + 2 * PLANE, acc.z);
                    atomicAdd(o + 3 * PLANE, acc.w);
                }
                acc = make_float4(0.f, 0.f, 0.f, 0.f);
                cur = vox;
            }
            float4 val = __ldcs(reinterpret_cast<const float4*>(xp + h * hstride));
            acc.x += val.x;
            acc.y += val.y;
            acc.z += val.z;
            acc.w += val.w;
        }
    }
    if (cur >= 0) {
        float* o = obase + cur;
        atomicAdd(o, acc.x);
        atomicAdd(o + PLANE, acc.y);
        atomicAdd(o + 2 * PLANE, acc.z);
        atomicAdd(o + 3 * PLANE, acc.w);
    }
}

// Persistent pool: 888 CTAs grid-stride over 1980 unit-blocks; loads of the
// next unit issue while prior unit's no-return REDs drain.
__global__ void __launch_bounds__(TPB, OCC)
pool_kernel(const float* __restrict__ x, float* __restrict__ out) {
    for (int unit = blockIdx.x; unit < UNITS; unit += NCTA) {
        pool_unit(unit * TPB + threadIdx.x, x, out);
    }
}

extern "C" void kernel_launch(void* const* d_in, const int* in_sizes, int n_in,
                              void* d_out, int out_size) {
    const float* x          = (const float*)d_in[0];
    const float* rots       = (const float*)d_in[1];
    const float* trans      = (const float*)d_in[2];
    const float* intrins    = (const float*)d_in[3];
    const float* post_rots  = (const float*)d_in[4];
    const float* post_trans = (const float*)d_in[5];
    float* out = (float*)d_out;

    int n4 = out_size / 4;
    prep_kernel<<<(n4 + TPB - 1) / TPB, TPB>>>((float4*)out, n4, rots, trans,
                                               intrins, post_rots, post_trans);

    pool_kernel<<<NCTA, TPB>>>(x, out);
}